// round 3
// baseline (speedup 1.0000x reference)
#include <cuda_runtime.h>
#include <cstdint>
#include <cstddef>

// ---------------------------------------------------------------------------
// QuantizedNN: 3-layer MLP with symmetric per-tensor fake quantization.
// The reference (XLA fp32) computes each matmul element as a single-
// accumulator ascending-k FMA chain over dequantized fp32 values, then one
// rounded bias add, then relu. Quantization bins amplify any deviation, so
// h1/h2 are computed here with EXACTLY that chain (SIMT FFMA GEMM).
// Layer 3 has no downstream quantization -> any accumulation order.
// ---------------------------------------------------------------------------

#define BATCH   16384
#define IN_DIM  784
#define HIDDEN  4096
#define OUT_DIM 10

#define TM 128
#define TN 128
#define TK 16

// absmax stats (float bits in unsigned for atomicMax):
// 0=x, 1=W1, 2=W2, 3=W3, 4=h1, 5=h2
__device__ unsigned g_absmax_bits[8];

// Scratch (device globals: allocation-free rule). "q" buffers hold
// dequantized fp32 values q*s (single rounding), matching the reference STE.
__device__ float g_xq [(size_t)BATCH  * IN_DIM];
__device__ float g_w1q[(size_t)HIDDEN * IN_DIM];
__device__ float g_w2q[(size_t)HIDDEN * HIDDEN];
__device__ float g_w3q[(size_t)OUT_DIM * HIDDEN];
__device__ float g_h1 [(size_t)BATCH * HIDDEN];
__device__ float g_h1q[(size_t)BATCH * HIDDEN];
__device__ float g_h2 [(size_t)BATCH * HIDDEN];
__device__ float g_h2q[(size_t)BATCH * HIDDEN];

__device__ __forceinline__ float load_scale(int idx, float nlev) {
    float amax = __uint_as_float(g_absmax_bits[idx]);
    // matches jnp.maximum(amax / n, 1e-8) in IEEE fp32
    return fmaxf(__fdiv_rn(amax, nlev), 1e-8f);
}

__global__ void init_stats_kernel() {
    if (threadIdx.x < 8) g_absmax_bits[threadIdx.x] = 0u;
}

__global__ void absmax_kernel(const float* __restrict__ x, int n4, int idx) {
    const float4* x4 = (const float4*)x;
    float m = 0.f;
    for (int i = blockIdx.x * blockDim.x + threadIdx.x; i < n4;
         i += gridDim.x * blockDim.x) {
        float4 v = x4[i];
        m = fmaxf(m, fmaxf(fmaxf(fabsf(v.x), fabsf(v.y)),
                           fmaxf(fabsf(v.z), fabsf(v.w))));
    }
#pragma unroll
    for (int o = 16; o; o >>= 1) m = fmaxf(m, __shfl_xor_sync(0xffffffffu, m, o));
    __shared__ float red[8];
    int lane = threadIdx.x & 31, w = threadIdx.x >> 5;
    if (lane == 0) red[w] = m;
    __syncthreads();
    if (threadIdx.x == 0) {
        float r = red[0];
        for (int i = 1; i < (int)(blockDim.x >> 5); i++) r = fmaxf(r, red[i]);
        atomicMax(&g_absmax_bits[idx], __float_as_uint(r));
    }
}

// out[r][c] = clip(round(in[r][c]/s), -n, n) * s   (all IEEE fp32, rn)
__global__ void quantize_kernel(const float* __restrict__ in,
                                float* __restrict__ out,
                                int K, int statIdx, float nlev) {
    int c = blockIdx.x * blockDim.x + threadIdx.x;
    int r = blockIdx.y;
    if (c >= K) return;
    float s = load_scale(statIdx, nlev);
    float v = in[(size_t)r * K + c];
    float q = fminf(fmaxf(rintf(__fdiv_rn(v, s)), -nlev), nlev);
    out[(size_t)r * K + c] = q * s;
}

// C[M,N] = A[M,K] @ B[N,K]^T + bias, optional relu, optional absmax(C).
// Each output element: single-accumulator fmaf chain, k ascending 0..K-1
// (bit-matches Eigen gebp / cuBLAS SIMT SGEMM), then one rounded bias add.
__global__ void __launch_bounds__(256)
gemm_chain_kernel(const float* __restrict__ A,
                  const float* __restrict__ B,
                  const float* __restrict__ bias,
                  float* __restrict__ C,
                  int M, int N, int K,
                  int iOut, int doRelu)
{
    __shared__ float As[2][TK][TM];   // transposed tiles, 16KB each pair
    __shared__ float Bs[2][TK][TN];

    const int tid = threadIdx.x;
    const int tx  = tid & 15;          // 16 col groups
    const int ty  = tid >> 4;          // 16 row groups
    const int bm  = blockIdx.y * TM;
    const int bn  = blockIdx.x * TN;

    const float* Ab = A + (size_t)bm * K;
    const float* Bb = B + (size_t)bn * K;

    float acc[8][8];
#pragma unroll
    for (int i = 0; i < 8; i++)
#pragma unroll
        for (int j = 0; j < 8; j++) acc[i][j] = 0.f;

    const int nkt = K / TK;

    // preload tile 0 into stage 0
    {
#pragma unroll
        for (int i = 0; i < 2; i++) {
            int idx = tid + i * 256;          // 0..511
            int row = idx >> 2, ch = idx & 3;
            float4 va = *(const float4*)(Ab + (size_t)row * K + ch * 4);
            As[0][ch * 4 + 0][row] = va.x;
            As[0][ch * 4 + 1][row] = va.y;
            As[0][ch * 4 + 2][row] = va.z;
            As[0][ch * 4 + 3][row] = va.w;
            float4 vb = *(const float4*)(Bb + (size_t)row * K + ch * 4);
            Bs[0][ch * 4 + 0][row] = vb.x;
            Bs[0][ch * 4 + 1][row] = vb.y;
            Bs[0][ch * 4 + 2][row] = vb.z;
            Bs[0][ch * 4 + 3][row] = vb.w;
        }
    }
    __syncthreads();

    int cur = 0;
    for (int kt = 0; kt < nkt; kt++) {
        float4 ra[2], rb[2];
        const bool more = (kt + 1 < nkt);
        if (more) {
            int kb = (kt + 1) * TK;
#pragma unroll
            for (int i = 0; i < 2; i++) {
                int idx = tid + i * 256;
                int row = idx >> 2, ch = idx & 3;
                ra[i] = *(const float4*)(Ab + (size_t)row * K + kb + ch * 4);
                rb[i] = *(const float4*)(Bb + (size_t)row * K + kb + ch * 4);
            }
        }

        // compute over stage cur: k ascending, single accumulator per output
        const float (*as)[TM] = As[cur];
        const float (*bs)[TN] = Bs[cur];
#pragma unroll
        for (int k = 0; k < TK; k++) {
            float af[8], bf[8];
            *(float4*)&af[0] = *(const float4*)&as[k][ty * 8];
            *(float4*)&af[4] = *(const float4*)&as[k][ty * 8 + 4];
            *(float4*)&bf[0] = *(const float4*)&bs[k][tx * 8];
            *(float4*)&bf[4] = *(const float4*)&bs[k][tx * 8 + 4];
#pragma unroll
            for (int i = 0; i < 8; i++)
#pragma unroll
                for (int j = 0; j < 8; j++)
                    acc[i][j] = fmaf(af[i], bf[j], acc[i][j]);
        }

        if (more) {
            int s = cur ^ 1;
#pragma unroll
            for (int i = 0; i < 2; i++) {
                int idx = tid + i * 256;
                int row = idx >> 2, ch = idx & 3;
                As[s][ch * 4 + 0][row] = ra[i].x;
                As[s][ch * 4 + 1][row] = ra[i].y;
                As[s][ch * 4 + 2][row] = ra[i].z;
                As[s][ch * 4 + 3][row] = ra[i].w;
                Bs[s][ch * 4 + 0][row] = rb[i].x;
                Bs[s][ch * 4 + 1][row] = rb[i].y;
                Bs[s][ch * 4 + 2][row] = rb[i].z;
                Bs[s][ch * 4 + 3][row] = rb[i].w;
            }
        }
        __syncthreads();
        cur ^= 1;
    }

    // Epilogue: v = acc + bias (one rounded add); optional relu; store; absmax
    float4 bv0 = *(const float4*)&bias[bn + tx * 8];
    float4 bv1 = *(const float4*)&bias[bn + tx * 8 + 4];
    const float bb[8] = {bv0.x, bv0.y, bv0.z, bv0.w, bv1.x, bv1.y, bv1.z, bv1.w};
    float lmax = 0.f;
#pragma unroll
    for (int i = 0; i < 8; i++) {
        int row = bm + ty * 8 + i;
        float v[8];
#pragma unroll
        for (int j = 0; j < 8; j++) {
            float t = acc[i][j] + bb[j];
            if (doRelu) t = fmaxf(t, 0.f);
            v[j] = t;
            lmax = fmaxf(lmax, fabsf(t));
        }
        *(float4*)&C[(size_t)row * N + bn + tx * 8]     = make_float4(v[0], v[1], v[2], v[3]);
        *(float4*)&C[(size_t)row * N + bn + tx * 8 + 4] = make_float4(v[4], v[5], v[6], v[7]);
    }
    if (iOut >= 0) {
#pragma unroll
        for (int o = 16; o; o >>= 1)
            lmax = fmaxf(lmax, __shfl_xor_sync(0xffffffffu, lmax, o));
        __shared__ float smax[8];
        int lane = tid & 31, wid = tid >> 5;
        if (lane == 0) smax[wid] = lmax;
        __syncthreads();
        if (tid == 0) {
            float m = smax[0];
#pragma unroll
            for (int i = 1; i < 8; i++) m = fmaxf(m, smax[i]);
            atomicMax(&g_absmax_bits[iOut], __float_as_uint(m));
        }
    }
}

// Layer 3: out[16384,10] = h2q @ w3q^T + b3 (no downstream quantization ->
// accumulation order free; warp-per-row dot products, W3 in smem).
__global__ void __launch_bounds__(512)
layer3_kernel(const float* __restrict__ b3, float* __restrict__ out)
{
    extern __shared__ float w3s[];   // [10][4096] fp32 = 160KB
    const int tid = threadIdx.x;
    {
        const float4* src = (const float4*)g_w3q;
        float4* dst = (float4*)w3s;
        for (int i = tid; i < OUT_DIM * HIDDEN / 4; i += 512) dst[i] = src[i];
    }
    __syncthreads();

    const int lane = tid & 31;
    const int w    = tid >> 5;
    const int m    = blockIdx.x * 16 + w;

    float acc[OUT_DIM];
#pragma unroll
    for (int n = 0; n < OUT_DIM; n++) acc[n] = 0.f;

    const float4* arow = (const float4*)(g_h2q + (size_t)m * HIDDEN);
    const float4* ws   = (const float4*)w3s;
    for (int k4 = lane; k4 < HIDDEN / 4; k4 += 32) {
        float4 a = arow[k4];
#pragma unroll
        for (int n = 0; n < OUT_DIM; n++) {
            float4 wv = ws[n * (HIDDEN / 4) + k4];
            acc[n] = fmaf(a.x, wv.x, acc[n]);
            acc[n] = fmaf(a.y, wv.y, acc[n]);
            acc[n] = fmaf(a.z, wv.z, acc[n]);
            acc[n] = fmaf(a.w, wv.w, acc[n]);
        }
    }
#pragma unroll
    for (int n = 0; n < OUT_DIM; n++)
#pragma unroll
        for (int o = 16; o; o >>= 1)
            acc[n] += __shfl_xor_sync(0xffffffffu, acc[n], o);

    if (lane == 0) {
#pragma unroll
        for (int n = 0; n < OUT_DIM; n++)
            out[(size_t)m * OUT_DIM + n] = acc[n] + b3[n];
    }
}

extern "C" void kernel_launch(void* const* d_in, const int* in_sizes, int n_in,
                              void* d_out, int out_size) {
    const float* x  = (const float*)d_in[0];
    const float* W1 = (const float*)d_in[1];
    const float* b1 = (const float*)d_in[2];
    const float* W2 = (const float*)d_in[3];
    const float* b2 = (const float*)d_in[4];
    const float* W3 = (const float*)d_in[5];
    const float* b3 = (const float*)d_in[6];
    float* out = (float*)d_out;

    void* p;
    cudaGetSymbolAddress(&p, g_xq);  float* xq  = (float*)p;
    cudaGetSymbolAddress(&p, g_w1q); float* w1q = (float*)p;
    cudaGetSymbolAddress(&p, g_w2q); float* w2q = (float*)p;
    cudaGetSymbolAddress(&p, g_w3q); float* w3q = (float*)p;
    cudaGetSymbolAddress(&p, g_h1);  float* h1  = (float*)p;
    cudaGetSymbolAddress(&p, g_h1q); float* h1q = (float*)p;
    cudaGetSymbolAddress(&p, g_h2);  float* h2  = (float*)p;
    cudaGetSymbolAddress(&p, g_h2q); float* h2q = (float*)p;

    const size_t l3_shm = (size_t)OUT_DIM * HIDDEN * sizeof(float);   // 160KB
    cudaFuncSetAttribute(layer3_kernel,
                         cudaFuncAttributeMaxDynamicSharedMemorySize, (int)l3_shm);

    init_stats_kernel<<<1, 32>>>();

    absmax_kernel<<<2048, 256>>>(x,  BATCH * IN_DIM / 4, 0);
    absmax_kernel<<<512,  256>>>(W1, HIDDEN * IN_DIM / 4, 1);
    absmax_kernel<<<2048, 256>>>(W2, HIDDEN * HIDDEN / 4, 2);
    absmax_kernel<<<40,   256>>>(W3, OUT_DIM * HIDDEN / 4, 3);

    { dim3 g((IN_DIM + 255) / 256, BATCH);
      quantize_kernel<<<g, 256>>>(x,  xq,  IN_DIM, 0, 7.f); }
    { dim3 g((IN_DIM + 255) / 256, HIDDEN);
      quantize_kernel<<<g, 256>>>(W1, w1q, IN_DIM, 1, 127.f); }
    { dim3 g(HIDDEN / 256, HIDDEN);
      quantize_kernel<<<g, 256>>>(W2, w2q, HIDDEN, 2, 127.f); }
    { dim3 g(HIDDEN / 256, OUT_DIM);
      quantize_kernel<<<g, 256>>>(W3, w3q, HIDDEN, 3, 127.f); }

    dim3 gg(HIDDEN / TN, BATCH / TM);  // (32, 128)

    // Layer 1 (K = 784 = 49 * 16)
    gemm_chain_kernel<<<gg, 256>>>(xq, w1q, b1, h1,
                                   BATCH, HIDDEN, IN_DIM, 4, 1);
    { dim3 g(HIDDEN / 256, BATCH);
      quantize_kernel<<<g, 256>>>(h1, h1q, HIDDEN, 4, 7.f); }

    // Layer 2 (K = 4096)
    gemm_chain_kernel<<<gg, 256>>>(h1q, w2q, b2, h2,
                                   BATCH, HIDDEN, HIDDEN, 5, 1);
    { dim3 g(HIDDEN / 256, BATCH);
      quantize_kernel<<<g, 256>>>(h2, h2q, HIDDEN, 5, 7.f); }

    // Layer 3
    layer3_kernel<<<BATCH / 16, 512, l3_shm>>>(b3, out);
}

// round 5
// speedup vs baseline: 4.7102x; 4.7102x over previous
#include <cuda_runtime.h>
#include <cuda_bf16.h>
#include <cstdint>
#include <cstddef>

// ---------------------------------------------------------------------------
// QuantizedNN hybrid v2 (bit-reproduces the round-3 serial-chain result):
//  - GEMMs on tensor cores over integer quantized values (exact, order-free)
//  - h-scale amax reconstructed BIT-EXACTLY by re-running the reference
//    ascending-k fmaf chain on the few argmax candidates
//  - near-bin-boundary elements repaired with the exact chain
// ---------------------------------------------------------------------------

#define BATCH   16384
#define IN_DIM  784
#define K1PAD   832          // 13 * 64 zero-padded K for layer 1
#define HIDDEN  4096
#define OUT_DIM 10

#define GBM 128
#define GBN 128
#define GBK 64
#define STAGE_ELEMS ((GBM + GBN) * GBK)   // 16384 bf16 per stage (32KB)

#define LIST_CAP (1u << 22)               // per-layer repair list capacity
#define TAU 1e-3f                          // bin-boundary margin (bin units)

// slots: 0=x,1=W1,2=W2,3=W3 | 4,5 = int amax h1,h2 | 6,7 = chain amax h1,h2
//        8,9 = repair counts L1,L2
__device__ unsigned g_absmax_bits[12];
__device__ unsigned g_list[2 * LIST_CAP];

__device__ __nv_bfloat16 g_xq [(size_t)BATCH  * K1PAD];
__device__ __nv_bfloat16 g_w1q[(size_t)HIDDEN * K1PAD];
__device__ __nv_bfloat16 g_w2q[(size_t)HIDDEN * HIDDEN];
__device__ __nv_bfloat16 g_w3q[(size_t)OUT_DIM * HIDDEN];
__device__ float         g_h1 [(size_t)BATCH * HIDDEN];
__device__ __nv_bfloat16 g_h1q[(size_t)BATCH * HIDDEN];
__device__ float         g_h2 [(size_t)BATCH * HIDDEN];
__device__ __nv_bfloat16 g_h2q[(size_t)BATCH * HIDDEN];

__device__ __forceinline__ float load_scale(int idx, float nlev) {
    float amax = __uint_as_float(g_absmax_bits[idx]);
    return fmaxf(__fdiv_rn(amax, nlev), 1e-8f);   // jnp.maximum(amax/n, 1e-8)
}

__global__ void init_stats_kernel() {
    if (threadIdx.x < 12) g_absmax_bits[threadIdx.x] = 0u;
}

__global__ void absmax_kernel(const float* __restrict__ x, int n4, int idx) {
    const float4* x4 = (const float4*)x;
    float m = 0.f;
    for (int i = blockIdx.x * blockDim.x + threadIdx.x; i < n4;
         i += gridDim.x * blockDim.x) {
        float4 v = x4[i];
        m = fmaxf(m, fmaxf(fmaxf(fabsf(v.x), fabsf(v.y)),
                           fmaxf(fabsf(v.z), fabsf(v.w))));
    }
#pragma unroll
    for (int o = 16; o; o >>= 1) m = fmaxf(m, __shfl_xor_sync(0xffffffffu, m, o));
    __shared__ float red[8];
    int lane = threadIdx.x & 31, w = threadIdx.x >> 5;
    if (lane == 0) red[w] = m;
    __syncthreads();
    if (threadIdx.x == 0) {
        float r = red[0];
        for (int i = 1; i < (int)(blockDim.x >> 5); i++) r = fmaxf(r, red[i]);
        atomicMax(&g_absmax_bits[idx], __float_as_uint(r));
    }
}

// integer quantize: out = clip(round(v/s),-n,n) as bf16 int; pad cols -> 0
__global__ void quantize_int_kernel(const float* __restrict__ in,
                                    __nv_bfloat16* __restrict__ out,
                                    int K, int Kpad, int statIdx, float nlev) {
    int c = blockIdx.x * blockDim.x + threadIdx.x;
    int r = blockIdx.y;
    if (c >= Kpad) return;
    float q = 0.f;
    if (c < K) {
        float s = load_scale(statIdx, nlev);
        float v = in[(size_t)r * K + c];
        q = fminf(fmaxf(rintf(__fdiv_rn(v, s)), -nlev), nlev);
    }
    out[(size_t)r * Kpad + c] = __float2bfloat16_rn(q);
}

// Exact reference-matching value: ascending-k single-accumulator fmaf chain
// over fl(q*s) values, + bias (one rounded add), relu. Identical fl ops to
// the round-3 SIMT GEMM for every element.
__device__ __forceinline__ float chain_value(const __nv_bfloat16* __restrict__ A,
                                             const __nv_bfloat16* __restrict__ W,
                                             const float* __restrict__ bias,
                                             int K, unsigned r, unsigned c,
                                             float sA, float sW) {
    const uint4* a4 = (const uint4*)(A + (size_t)r * K);
    const uint4* w4 = (const uint4*)(W + (size_t)c * K);
    float acc = 0.f;
    for (int kc = 0; kc < K / 8; kc++) {
        uint4 ua = __ldg(&a4[kc]);
        uint4 uw = __ldg(&w4[kc]);
        const __nv_bfloat162* pa = (const __nv_bfloat162*)&ua;
        const __nv_bfloat162* pw = (const __nv_bfloat162*)&uw;
#pragma unroll
        for (int j = 0; j < 4; j++) {
            float2 fa = __bfloat1622float2(pa[j]);
            float2 fw = __bfloat1622float2(pw[j]);
            acc = fmaf(__fmul_rn(fa.x, sA), __fmul_rn(fw.x, sW), acc);
            acc = fmaf(__fmul_rn(fa.y, sA), __fmul_rn(fw.y, sW), acc);
        }
    }
    return fmaxf(__fadd_rn(acc, __ldg(&bias[c])), 0.f);
}

// Reconstruct the chain amax bit-exactly: every element whose int-GEMM value
// is within 4e-6 rel of the int amax gets its chain value computed; max of
// those == max of chain over all elements (deviation bound ~1e-6).
__global__ void chain_amax_kernel(const float* __restrict__ h,
                                  const __nv_bfloat16* __restrict__ Aq,
                                  const __nv_bfloat16* __restrict__ Wq,
                                  const float* __restrict__ bias,
                                  int K, int intSlot, int chainSlot,
                                  int iA, float nA, int iW, float nW) {
    float amax = __uint_as_float(g_absmax_bits[intSlot]);
    float thr  = amax * (1.0f - 4e-6f);
    const float sA = load_scale(iA, nA);
    const float sW = load_scale(iW, nW);
    const int NEL = BATCH * HIDDEN;
    for (int idx = blockIdx.x * blockDim.x + threadIdx.x; idx < NEL;
         idx += gridDim.x * blockDim.x) {
        if (h[idx] >= thr) {
            unsigned r = (unsigned)idx >> 12, c = (unsigned)idx & 4095u;
            float hv = chain_value(Aq, Wq, bias, K, r, c, sA, sW);
            atomicMax(&g_absmax_bits[chainSlot], __float_as_uint(hv));
        }
    }
}

// quantize h (int-GEMM values) with the CHAIN scale; flag near-boundary.
__global__ void quantize_detect_kernel(const float* __restrict__ h,
                                       __nv_bfloat16* __restrict__ qout,
                                       int chainSlot, int cntSlot,
                                       unsigned listBase) {
    int idx = blockIdx.x * blockDim.x + threadIdx.x;
    float s = load_scale(chainSlot, 7.f);
    float t = __fdiv_rn(h[idx], s);
    float r = rintf(t);
    float q = fminf(fmaxf(r, -7.f), 7.f);
    qout[idx] = __float2bfloat16_rn(q);
    if (fabsf(t - r) > 0.5f - TAU) {
        unsigned p = atomicAdd(&g_absmax_bits[cntSlot], 1u);
        if (p < LIST_CAP) g_list[listBase + p] = (unsigned)idx;
    }
}

// repair: recompute flagged elements with the exact chain, re-bin, overwrite.
__global__ void repair_kernel(const __nv_bfloat16* __restrict__ Aq,
                              const __nv_bfloat16* __restrict__ Wq,
                              const float* __restrict__ bias,
                              __nv_bfloat16* __restrict__ qout,
                              int K, int cntSlot, unsigned listBase,
                              int iA, float nA, int iW, float nW,
                              int chainSlot) {
    unsigned cnt = g_absmax_bits[cntSlot];
    if (cnt > LIST_CAP) cnt = LIST_CAP;
    const float sA = load_scale(iA, nA);
    const float sW = load_scale(iW, nW);
    const float sO = load_scale(chainSlot, 7.f);
    for (unsigned i = blockIdx.x * blockDim.x + threadIdx.x; i < cnt;
         i += gridDim.x * blockDim.x) {
        unsigned idx = g_list[listBase + i];
        unsigned r = idx >> 12, c = idx & 4095u;
        float hv = chain_value(Aq, Wq, bias, K, r, c, sA, sW);
        float t  = __fdiv_rn(hv, sO);
        float q  = fminf(fmaxf(rintf(t), -7.f), 7.f);
        qout[idx] = __float2bfloat16_rn(q);
    }
}

__device__ __forceinline__ uint32_t smem_u32(const void* p) {
    return (uint32_t)__cvta_generic_to_shared(p);
}

__device__ __forceinline__ void load_stage(__nv_bfloat16* stage,
                                           const __nv_bfloat16* __restrict__ A,
                                           const __nv_bfloat16* __restrict__ B,
                                           int K, int bm0, int bn0, int kt,
                                           int lrow, int lcol)
{
    __nv_bfloat16* as = stage;
    __nv_bfloat16* bs = stage + GBM * GBK;
    const int kbase = kt * GBK + (lcol << 3);
#pragma unroll
    for (int i = 0; i < 4; i++) {
        int r = i * 32 + lrow;
        uint32_t dst = smem_u32(as + r * GBK + ((lcol ^ (r & 7)) << 3));
        asm volatile("cp.async.cg.shared.global [%0], [%1], 16;\n"
                     :: "r"(dst), "l"(A + (size_t)(bm0 + r) * K + kbase));
    }
#pragma unroll
    for (int i = 0; i < 4; i++) {
        int r = i * 32 + lrow;
        uint32_t dst = smem_u32(bs + r * GBK + ((lcol ^ (r & 7)) << 3));
        asm volatile("cp.async.cg.shared.global [%0], [%1], 16;\n"
                     :: "r"(dst), "l"(B + (size_t)(bn0 + r) * K + kbase));
    }
    asm volatile("cp.async.commit_group;\n" ::: "memory");
}

// C = sc * (Aq @ Bq^T) + bias, relu, int amax -> iOutInt.
__global__ void __launch_bounds__(256, 2)
gemm_bf16_kernel(const __nv_bfloat16* __restrict__ A,
                 const __nv_bfloat16* __restrict__ B,
                 const float* __restrict__ bias,
                 float* __restrict__ C,
                 int M, int N, int K,
                 int iA, float nA, int iW, float nW,
                 int iOutInt)
{
    extern __shared__ __nv_bfloat16 smem[];
    const int tid  = threadIdx.x;
    const int lane = tid & 31;
    const int wid  = tid >> 5;
    const int wm   = wid >> 2;
    const int wn   = wid & 3;
    const int bm0  = blockIdx.y * GBM;
    const int bn0  = blockIdx.x * GBN;
    const int lrow = tid >> 3;
    const int lcol = tid & 7;

    float acc[4][4][4];
#pragma unroll
    for (int i = 0; i < 4; i++)
#pragma unroll
        for (int j = 0; j < 4; j++)
#pragma unroll
            for (int v = 0; v < 4; v++) acc[i][j][v] = 0.f;

    const int nkt = K / GBK;
    load_stage(smem, A, B, K, bm0, bn0, 0, lrow, lcol);

    for (int kt = 0; kt < nkt; kt++) {
        if (kt + 1 < nkt) {
            load_stage(smem + ((kt + 1) & 1) * STAGE_ELEMS, A, B, K, bm0, bn0,
                       kt + 1, lrow, lcol);
            asm volatile("cp.async.wait_group 1;\n" ::: "memory");
        } else {
            asm volatile("cp.async.wait_group 0;\n" ::: "memory");
        }
        __syncthreads();

        const __nv_bfloat16* as = smem + (kt & 1) * STAGE_ELEMS;
        const __nv_bfloat16* bs = as + GBM * GBK;

#pragma unroll
        for (int s = 0; s < 4; s++) {
            uint32_t af[4][4];
#pragma unroll
            for (int im = 0; im < 4; im++) {
                int r  = wm * 64 + im * 16 + (lane & 15);
                int ch = (2 * s + (lane >> 4)) ^ (r & 7);
                uint32_t addr = smem_u32(as + r * GBK + ch * 8);
                asm volatile(
                    "ldmatrix.sync.aligned.m8n8.x4.shared.b16 {%0,%1,%2,%3}, [%4];"
                    : "=r"(af[im][0]), "=r"(af[im][1]), "=r"(af[im][2]), "=r"(af[im][3])
                    : "r"(addr));
            }
            uint32_t bfr[4][2];
#pragma unroll
            for (int jn = 0; jn < 4; jn++) {
                int idx = lane & 15;
                int r   = wn * 32 + jn * 8 + (idx & 7);
                int ch  = (2 * s + (idx >> 3)) ^ (r & 7);
                uint32_t addr = smem_u32(bs + r * GBK + ch * 8);
                asm volatile(
                    "ldmatrix.sync.aligned.m8n8.x2.shared.b16 {%0,%1}, [%2];"
                    : "=r"(bfr[jn][0]), "=r"(bfr[jn][1])
                    : "r"(addr));
            }
#pragma unroll
            for (int im = 0; im < 4; im++)
#pragma unroll
                for (int jn = 0; jn < 4; jn++) {
                    asm volatile(
                        "mma.sync.aligned.m16n8k16.row.col.f32.bf16.bf16.f32 "
                        "{%0,%1,%2,%3}, {%4,%5,%6,%7}, {%8,%9}, {%0,%1,%2,%3};"
                        : "+f"(acc[im][jn][0]), "+f"(acc[im][jn][1]),
                          "+f"(acc[im][jn][2]), "+f"(acc[im][jn][3])
                        : "r"(af[im][0]), "r"(af[im][1]), "r"(af[im][2]), "r"(af[im][3]),
                          "r"(bfr[jn][0]), "r"(bfr[jn][1]));
                }
        }
        __syncthreads();
    }

    const float sc = load_scale(iA, nA) * load_scale(iW, nW);
    const int g = lane >> 2, t = lane & 3;
    float lmax = 0.f;
#pragma unroll
    for (int im = 0; im < 4; im++) {
#pragma unroll
        for (int jn = 0; jn < 4; jn++) {
            int row = bm0 + wm * 64 + im * 16 + g;
            int col = bn0 + wn * 32 + jn * 8 + 2 * t;
            float bv0 = bias[col], bv1 = bias[col + 1];
            float v00 = fmaxf(fmaf(acc[im][jn][0], sc, bv0), 0.f);
            float v01 = fmaxf(fmaf(acc[im][jn][1], sc, bv1), 0.f);
            float v10 = fmaxf(fmaf(acc[im][jn][2], sc, bv0), 0.f);
            float v11 = fmaxf(fmaf(acc[im][jn][3], sc, bv1), 0.f);
            *(float2*)&C[(size_t)row * N + col]       = make_float2(v00, v01);
            *(float2*)&C[(size_t)(row + 8) * N + col] = make_float2(v10, v11);
            lmax = fmaxf(lmax, fmaxf(fmaxf(v00, v01), fmaxf(v10, v11)));
        }
    }
#pragma unroll
    for (int o = 16; o; o >>= 1)
        lmax = fmaxf(lmax, __shfl_xor_sync(0xffffffffu, lmax, o));
    __shared__ float smax[8];
    if (lane == 0) smax[wid] = lmax;
    __syncthreads();
    if (tid == 0) {
        float m = smax[0];
#pragma unroll
        for (int i = 1; i < 8; i++) m = fmaxf(m, smax[i]);
        atomicMax(&g_absmax_bits[iOutInt], __float_as_uint(m));
    }
}

// Layer 3: exact integer warp-dot, out = sc*acc + b3 (order-free, no quant).
__global__ void __launch_bounds__(512)
layer3_kernel(const float* __restrict__ b3, float* __restrict__ out)
{
    extern __shared__ __nv_bfloat16 w3s[];   // [10][4096] bf16 = 80KB
    const int tid = threadIdx.x;
    {
        const uint4* src = (const uint4*)g_w3q;
        uint4* dst = (uint4*)w3s;
        for (int i = tid; i < OUT_DIM * HIDDEN / 8; i += 512) dst[i] = src[i];
    }
    __syncthreads();

    const int lane = tid & 31;
    const int w    = tid >> 5;
    const int m    = blockIdx.x * 16 + w;

    float acc[OUT_DIM];
#pragma unroll
    for (int n = 0; n < OUT_DIM; n++) acc[n] = 0.f;

    const uint32_t* arow = (const uint32_t*)(g_h2q + (size_t)m * HIDDEN);
    const uint32_t* ws   = (const uint32_t*)w3s;
    for (int k2 = lane; k2 < HIDDEN / 2; k2 += 32) {
        uint32_t av = arow[k2];
        float a0 = __uint_as_float(av << 16);
        float a1 = __uint_as_float(av & 0xffff0000u);
#pragma unroll
        for (int n = 0; n < OUT_DIM; n++) {
            uint32_t wv = ws[n * (HIDDEN / 2) + k2];
            acc[n] = fmaf(a0, __uint_as_float(wv << 16), acc[n]);
            acc[n] = fmaf(a1, __uint_as_float(wv & 0xffff0000u), acc[n]);
        }
    }
#pragma unroll
    for (int n = 0; n < OUT_DIM; n++)
#pragma unroll
        for (int o = 16; o; o >>= 1)
            acc[n] += __shfl_xor_sync(0xffffffffu, acc[n], o);

    if (lane == 0) {
        float sc = load_scale(7, 7.f) * load_scale(3, 127.f);
#pragma unroll
        for (int n = 0; n < OUT_DIM; n++)
            out[(size_t)m * OUT_DIM + n] = fmaf(acc[n], sc, b3[n]);
    }
}

extern "C" void kernel_launch(void* const* d_in, const int* in_sizes, int n_in,
                              void* d_out, int out_size) {
    const float* x  = (const float*)d_in[0];
    const float* W1 = (const float*)d_in[1];
    const float* b1 = (const float*)d_in[2];
    const float* W2 = (const float*)d_in[3];
    const float* b2 = (const float*)d_in[4];
    const float* W3 = (const float*)d_in[5];
    const float* b3 = (const float*)d_in[6];
    float* out = (float*)d_out;

    void* p;
    cudaGetSymbolAddress(&p, g_xq);  __nv_bfloat16* xq  = (__nv_bfloat16*)p;
    cudaGetSymbolAddress(&p, g_w1q); __nv_bfloat16* w1q = (__nv_bfloat16*)p;
    cudaGetSymbolAddress(&p, g_w2q); __nv_bfloat16* w2q = (__nv_bfloat16*)p;
    cudaGetSymbolAddress(&p, g_w3q); __nv_bfloat16* w3q = (__nv_bfloat16*)p;
    cudaGetSymbolAddress(&p, g_h1);  float*         h1  = (float*)p;
    cudaGetSymbolAddress(&p, g_h1q); __nv_bfloat16* h1q = (__nv_bfloat16*)p;
    cudaGetSymbolAddress(&p, g_h2);  float*         h2  = (float*)p;
    cudaGetSymbolAddress(&p, g_h2q); __nv_bfloat16* h2q = (__nv_bfloat16*)p;

    const size_t gemm_shm = (size_t)2 * STAGE_ELEMS * sizeof(__nv_bfloat16); // 64KB
    const size_t l3_shm   = (size_t)OUT_DIM * HIDDEN * sizeof(__nv_bfloat16); // 80KB
    cudaFuncSetAttribute(gemm_bf16_kernel,
                         cudaFuncAttributeMaxDynamicSharedMemorySize, (int)gemm_shm);
    cudaFuncSetAttribute(layer3_kernel,
                         cudaFuncAttributeMaxDynamicSharedMemorySize, (int)l3_shm);

    init_stats_kernel<<<1, 32>>>();

    absmax_kernel<<<2048, 256>>>(x,  BATCH * IN_DIM / 4, 0);
    absmax_kernel<<<512,  256>>>(W1, HIDDEN * IN_DIM / 4, 1);
    absmax_kernel<<<2048, 256>>>(W2, HIDDEN * HIDDEN / 4, 2);
    absmax_kernel<<<40,   256>>>(W3, OUT_DIM * HIDDEN / 4, 3);

    { dim3 g((K1PAD + 255) / 256, BATCH);
      quantize_int_kernel<<<g, 256>>>(x,  xq,  IN_DIM, K1PAD, 0, 7.f); }
    { dim3 g((K1PAD + 255) / 256, HIDDEN);
      quantize_int_kernel<<<g, 256>>>(W1, w1q, IN_DIM, K1PAD, 1, 127.f); }
    { dim3 g(HIDDEN / 256, HIDDEN);
      quantize_int_kernel<<<g, 256>>>(W2, w2q, HIDDEN, HIDDEN, 2, 127.f); }
    { dim3 g(HIDDEN / 256, OUT_DIM);
      quantize_int_kernel<<<g, 256>>>(W3, w3q, HIDDEN, HIDDEN, 3, 127.f); }

    dim3 gg(HIDDEN / GBN, BATCH / GBM);  // (32, 128)
    const int NEL = BATCH * HIDDEN;      // 2^26

    // ---- Layer 1 ----
    gemm_bf16_kernel<<<gg, 256, gemm_shm>>>(xq, w1q, b1, h1,
                                            BATCH, HIDDEN, K1PAD,
                                            0, 7.f, 1, 127.f, 4);
    chain_amax_kernel<<<2048, 256>>>(h1, xq, w1q, b1, K1PAD, 4, 6,
                                     0, 7.f, 1, 127.f);
    quantize_detect_kernel<<<NEL / 256, 256>>>(h1, h1q, 6, 8, 0u);
    repair_kernel<<<2048, 256>>>(xq, w1q, b1, h1q, K1PAD, 8, 0u,
                                 0, 7.f, 1, 127.f, 6);

    // ---- Layer 2 ----
    gemm_bf16_kernel<<<gg, 256, gemm_shm>>>(h1q, w2q, b2, h2,
                                            BATCH, HIDDEN, HIDDEN,
                                            6, 7.f, 2, 127.f, 5);
    chain_amax_kernel<<<2048, 256>>>(h2, h1q, w2q, b2, HIDDEN, 5, 7,
                                     6, 7.f, 2, 127.f);
    quantize_detect_kernel<<<NEL / 256, 256>>>(h2, h2q, 7, 9, LIST_CAP);
    repair_kernel<<<2048, 256>>>(h1q, w2q, b2, h2q, HIDDEN, 9, LIST_CAP,
                                 6, 7.f, 2, 127.f, 7);

    // ---- Layer 3 ----
    layer3_kernel<<<BATCH / 16, 512, l3_shm>>>(b3, out);
}